// round 17
// baseline (speedup 1.0000x reference)
#include <cuda_runtime.h>
#include <cuda_fp16.h>
#include <math.h>
#include <stdint.h>

#define T_TOKENS 1024
#define H_DIM    2048
#define I_DIM    1408
#define SI_DIM   5632
#define NE       8

// ---------------------------------------------------------------------------
// Scratch (__device__ globals; no cudaMalloc allowed)
// ---------------------------------------------------------------------------
__device__ int   g_cnt[NE];
__device__ int   g_tok [NE * T_TOKENS];
__device__ int   g_slot[NE * T_TOKENS];
__device__ float g_wt  [NE * T_TOKENS];
__device__ float g_sgate[T_TOKENS];

__device__ __half g_hid[(size_t)T_TOKENS * H_DIM];
__device__ __half g_act[(size_t)NE * T_TOKENS * I_DIM];
__device__ __half g_shact[(size_t)T_TOKENS * SI_DIM];
__device__ float  g_contrib[(size_t)T_TOKENS * 2 * H_DIM];

__device__ __half g_wg16[(size_t)NE * H_DIM * I_DIM];
__device__ __half g_wu16[(size_t)NE * H_DIM * I_DIM];
__device__ __half g_wd16[(size_t)NE * I_DIM * H_DIM];
__device__ __half g_swg16[(size_t)H_DIM * SI_DIM];
__device__ __half g_swu16[(size_t)H_DIM * SI_DIM];
__device__ __half g_swd16[(size_t)SI_DIM * H_DIM];

// ---------------------------------------------------------------------------
__global__ void zero_cnt_kernel() {
    if (threadIdx.x < NE) g_cnt[threadIdx.x] = 0;
}

__global__ __launch_bounds__(256) void router_kernel(
    const float* __restrict__ hidden,
    const float* __restrict__ gate_w,
    const float* __restrict__ shared_gate_w,
    float* __restrict__ out_logits)
{
    const int t = blockIdx.x;
    __shared__ float sh[H_DIM];
    __shared__ float slog[NE];
    __shared__ float sred[256];

    const float* hrow = hidden + (size_t)t * H_DIM;
    for (int i = threadIdx.x; i < H_DIM; i += 256) sh[i] = hrow[i];
    __syncthreads();

    const int warp = threadIdx.x >> 5;
    const int lane = threadIdx.x & 31;

    float sum = 0.f;
    for (int k = lane; k < H_DIM; k += 32) sum += sh[k] * gate_w[k * NE + warp];
    #pragma unroll
    for (int o = 16; o; o >>= 1) sum += __shfl_down_sync(0xffffffffu, sum, o);
    if (lane == 0) slog[warp] = sum;

    float s2 = 0.f;
    for (int k = threadIdx.x; k < H_DIM; k += 256) s2 += sh[k] * shared_gate_w[k];
    sred[threadIdx.x] = s2;
    __syncthreads();
    for (int st = 128; st; st >>= 1) {
        if (threadIdx.x < st) sred[threadIdx.x] += sred[threadIdx.x + st];
        __syncthreads();
    }

    if (threadIdx.x == 0) {
        float lg[NE];
        float mx = -1e30f;
        #pragma unroll
        for (int e = 0; e < NE; ++e) { lg[e] = slog[e]; mx = fmaxf(mx, lg[e]); }
        float p[NE]; float den = 0.f;
        #pragma unroll
        for (int e = 0; e < NE; ++e) { p[e] = expf(lg[e] - mx); den += p[e]; }
        float inv = 1.f / den;
        #pragma unroll
        for (int e = 0; e < NE; ++e) {
            p[e] *= inv;
            out_logits[(size_t)t * NE + e] = lg[e];
        }
        int i0 = 0;
        #pragma unroll
        for (int e = 1; e < NE; ++e) if (p[e] > p[i0]) i0 = e;
        int i1 = -1;
        #pragma unroll
        for (int e = 0; e < NE; ++e) {
            if (e == i0) continue;
            if (i1 < 0 || p[e] > p[i1]) i1 = e;
        }
        int pos0 = atomicAdd(&g_cnt[i0], 1);
        g_tok [i0 * T_TOKENS + pos0] = t;
        g_slot[i0 * T_TOKENS + pos0] = 0;
        g_wt  [i0 * T_TOKENS + pos0] = p[i0];
        int pos1 = atomicAdd(&g_cnt[i1], 1);
        g_tok [i1 * T_TOKENS + pos1] = t;
        g_slot[i1 * T_TOKENS + pos1] = 1;
        g_wt  [i1 * T_TOKENS + pos1] = p[i1];

        g_sgate[t] = 1.f / (1.f + expf(-sred[0]));
    }
}

// ---------------------------------------------------------------------------
__global__ __launch_bounds__(256) void cvt_kernel(
    const float* __restrict__ src, __half* __restrict__ dst, int n4)
{
    for (int i = blockIdx.x * 256 + threadIdx.x; i < n4; i += gridDim.x * 256) {
        float4 v = ((const float4*)src)[i];
        ((__half2*)dst)[2 * i]     = __floats2half2_rn(v.x, v.y);
        ((__half2*)dst)[2 * i + 1] = __floats2half2_rn(v.z, v.w);
    }
}

// ---------------------------------------------------------------------------
// helpers
// ---------------------------------------------------------------------------
__device__ __forceinline__ uint32_t smem_u32(const void* p) {
    return (uint32_t)__cvta_generic_to_shared(p);
}
__device__ __forceinline__ void ldsm_x4(uint32_t* r, uint32_t a) {
    asm volatile("ldmatrix.sync.aligned.m8n8.x4.shared.b16 {%0,%1,%2,%3}, [%4];"
                 : "=r"(r[0]), "=r"(r[1]), "=r"(r[2]), "=r"(r[3]) : "r"(a));
}
__device__ __forceinline__ void ldsm_x4_t(uint32_t* r, uint32_t a) {
    asm volatile("ldmatrix.sync.aligned.m8n8.x4.trans.shared.b16 {%0,%1,%2,%3}, [%4];"
                 : "=r"(r[0]), "=r"(r[1]), "=r"(r[2]), "=r"(r[3]) : "r"(a));
}
__device__ __forceinline__ void mma16816(float* d, const uint32_t* a, uint32_t b0, uint32_t b1) {
    asm("mma.sync.aligned.m16n8k16.row.col.f32.f16.f16.f32 "
        "{%0,%1,%2,%3}, {%4,%5,%6,%7}, {%8,%9}, {%0,%1,%2,%3};"
        : "+f"(d[0]), "+f"(d[1]), "+f"(d[2]), "+f"(d[3])
        : "r"(a[0]), "r"(a[1]), "r"(a[2]), "r"(a[3]), "r"(b0), "r"(b1));
}
__device__ __forceinline__ uint32_t h2bits(__half2 h) {
    return *reinterpret_cast<uint32_t*>(&h);
}

#define CP16(dst, src) \
    asm volatile("cp.async.cg.shared.global [%0], [%1], 16;" :: "r"(dst), "l"(src) : "memory")
#define CP_COMMIT() asm volatile("cp.async.commit_group;" ::: "memory")
#define CP_WAIT(n)  asm volatile("cp.async.wait_group %0;" :: "n"(n) : "memory")

#define ASTRIDE 80
#define A_BYTES 10240

// ---------------------------------------------------------------------------
// FUSED gate+up GEMM. 128 threads = 4 warps (2m x 2n), warp tile 64x64.
// CTA tile 128 x 128 = [gate 64 | up 64]. 3-stage cp.async pipeline.
// blockIdx.x < 704: shared tile; else expert tile (gathered rows).
// ---------------------------------------------------------------------------
#define GU_SH_BLOCKS (SI_DIM / 64 * (T_TOKENS / 128))            // 704
#define GU_EXP_BLOCKS (I_DIM / 64 * (T_TOKENS / 128) * NE)       // 1408

__global__ void __launch_bounds__(128, 2) gateup_fused(
    const __half* __restrict__ A,
    const __half* __restrict__ wg, const __half* __restrict__ wu,
    const __half* __restrict__ swg, const __half* __restrict__ swu,
    __half* __restrict__ actO, __half* __restrict__ shO)
{
    constexpr int NW = 64, NJ = 8;
    constexpr int BSTR = 272, BSZ = 32 * BSTR;      // 8704
    constexpr int STG = A_BYTES + BSZ;              // 18944
    constexpr int K = H_DIM;

    int isExp, e, m0, n0, Ntot;
    const __half *B0, *B1;
    __half *oP;
    {
        const int bid = blockIdx.x;
        if (bid < GU_SH_BLOCKS) {
            isExp = 0; e = 0;
            m0 = (bid / (SI_DIM / 64)) * 128;
            n0 = (bid % (SI_DIM / 64)) * 64;
            Ntot = SI_DIM; B0 = swg; B1 = swu; oP = shO;
        } else {
            const int t = bid - GU_SH_BLOCKS;
            const int per_e = (I_DIM / 64) * (T_TOKENS / 128);   // 176
            isExp = 1; e = t / per_e;
            const int rem = t % per_e;
            m0 = (rem / (I_DIM / 64)) * 128;
            n0 = (rem % (I_DIM / 64)) * 64;
            Ntot = I_DIM; B0 = wg; B1 = wu; oP = actO;
        }
    }
    const int cnt = isExp ? g_cnt[e] : T_TOKENS;
    if (m0 >= cnt) return;

    extern __shared__ char db[];
    __shared__ int s_tok[128];

    const int tid  = threadIdx.x;
    const int lane = tid & 31;
    const int warp = tid >> 5;       // 0..3
    const int wm = warp & 1;         // m: wm*64
    const int wn = warp >> 1;        // n: wn*64

    if (isExp) {
        int gm = m0 + tid;
        s_tok[tid] = (gm < cnt) ? g_tok[e * T_TOKENS + gm] : 0;
    }
    __syncthreads();

    // ---- A loader: thread -> row tid, 32 k halves (4x CP16) ----
    size_t arow = isExp ? (size_t)s_tok[tid] : (size_t)(m0 + tid);
    const __half* aP = A + arow * K;
    const uint32_t aDst = smem_u32(db) + (uint32_t)(tid * ASTRIDE);

    // ---- B loader: k-row tid>>2, 32 halves at (tid&3)*32 (4x CP16) ----
    const int bkr = tid >> 2;
    const int seg = (tid & 3) * 32;
    const size_t eoff = isExp ? (size_t)e * K * Ntot : 0;
    const __half* BP = (seg < NW ? B0 + eoff + n0 + seg : B1 + eoff + n0 + seg - NW)
                       + (size_t)bkr * Ntot;
    const uint32_t bDst = smem_u32(db) + (uint32_t)(A_BYTES + bkr * BSTR + seg * 2);

    auto issue = [&](int k0, int s) {
        const uint32_t so = (uint32_t)(s * STG);
        #pragma unroll
        for (int i = 0; i < 4; ++i) CP16(aDst + so + i * 16, aP + k0 + i * 8);
        const __half* bp = BP + (size_t)k0 * Ntot;
        #pragma unroll
        for (int i = 0; i < 4; ++i) CP16(bDst + so + i * 16, bp + i * 8);
    };

    float acc[4][NJ][4];
    #pragma unroll
    for (int i = 0; i < 4; ++i)
        #pragma unroll
        for (int j = 0; j < NJ; ++j)
            #pragma unroll
            for (int v = 0; v < 4; ++v) acc[i][j][v] = 0.f;

    const int grp = lane >> 3;
    const int gl  = lane & 7;
    const int a_row_off = (grp & 1) * 8 + gl;
    const int a_col_off = (grp >> 1) * 8;
    const int b_row_off = (grp & 1) * 8 + gl;
    const int b_col_off = (grp >> 1) * 8;

    const int C = K / 32;
    issue(0, 0); CP_COMMIT();
    issue(32, 1); CP_COMMIT();
    issue(64, 2); CP_COMMIT();

    for (int c = 0; c < C; ++c) {
        CP_WAIT(2);
        __syncthreads();

        const uint32_t base = smem_u32(db) + (uint32_t)((c % 3) * STG);
        #pragma unroll
        for (int ks = 0; ks < 32; ks += 16) {
            uint32_t ah[4][4];
            #pragma unroll
            for (int mi = 0; mi < 4; ++mi) {
                const uint32_t ra = base + (uint32_t)((wm * 64 + mi * 16 + a_row_off) * ASTRIDE + (ks + a_col_off) * 2);
                ldsm_x4(ah[mi], ra);
            }
            #pragma unroll
            for (int g = 0; g < 4; ++g) {
                uint32_t bh[4];
                const uint32_t rb = base + (uint32_t)(A_BYTES + (ks + b_row_off) * BSTR + (wn * 64 + g * 16 + b_col_off) * 2);
                ldsm_x4_t(bh, rb);
                #pragma unroll
                for (int mi = 0; mi < 4; ++mi)
                    #pragma unroll
                    for (int half = 0; half < 2; ++half)
                        mma16816(acc[mi][g * 2 + half], ah[mi], bh[half * 2], bh[half * 2 + 1]);
            }
        }
        __syncthreads();
        if (c + 3 < C) issue((c + 3) * 32, c % 3);
        CP_COMMIT();
    }

    // ---- epilogue: silu(g)*u -> fp16 ----
    constexpr int EXS = NW + 8;
    float* exch = (float*)db;
    if (wn == 1) {
        #pragma unroll
        for (int mi = 0; mi < 4; ++mi)
            #pragma unroll
            for (int nj = 0; nj < NJ; ++nj) {
                const int cl = nj * 8 + (lane & 3) * 2;
                #pragma unroll
                for (int h = 0; h < 2; ++h) {
                    const int rl = wm * 64 + mi * 16 + (lane >> 2) + h * 8;
                    exch[rl * EXS + cl]     = acc[mi][nj][h * 2];
                    exch[rl * EXS + cl + 1] = acc[mi][nj][h * 2 + 1];
                }
            }
    }
    __syncthreads();
    if (wn == 0) {
        #pragma unroll
        for (int mi = 0; mi < 4; ++mi)
            #pragma unroll
            for (int h = 0; h < 2; ++h) {
                const int rl = wm * 64 + mi * 16 + (lane >> 2) + h * 8;
                const int r = m0 + rl;
                if (isExp && r >= cnt) continue;
                const size_t row = (isExp ? (size_t)e * T_TOKENS : 0) + r;
                #pragma unroll
                for (int nj = 0; nj < NJ; ++nj) {
                    const int cl = nj * 8 + (lane & 3) * 2;
                    const float g0 = acc[mi][nj][h * 2];
                    const float g1 = acc[mi][nj][h * 2 + 1];
                    const float u0 = exch[rl * EXS + cl];
                    const float u1 = exch[rl * EXS + cl + 1];
                    const float a0 = (g0 / (1.f + expf(-g0))) * u0;
                    const float a1 = (g1 / (1.f + expf(-g1))) * u1;
                    *(uint32_t*)(oP + row * Ntot + n0 + cl) = h2bits(__floats2half2_rn(a0, a1));
                }
            }
    }
}

// ---------------------------------------------------------------------------
// Down GEMM: 128 threads, 4 warps (2m x 2n), warp tile 64 x TILE_N/2.
// EPI=1: expert scatter x weight. EPI=2: shared combine -> outF.
// ---------------------------------------------------------------------------
template<int AEXP, int EPI, int TILE_N>
__global__ void __launch_bounds__(128, 2) down_gemm(
    const __half* __restrict__ A,
    const __half* __restrict__ B0,
    float* __restrict__ outF, int K, int Ntot)
{
    constexpr int NW   = TILE_N / 2;
    constexpr int NJ   = NW / 8;
    constexpr int CPT  = TILE_N / 4;            // halves per B loader thread
    constexpr int NCP  = CPT / 8;               // CP16s per B loader thread
    constexpr int BSTR = TILE_N * 2 + 16;
    constexpr int BSZ  = 32 * BSTR;
    constexpr int STG  = A_BYTES + BSZ;

    const int e  = blockIdx.z;
    const int m0 = blockIdx.y * 128;
    const int n0 = blockIdx.x * TILE_N;
    const int cnt = AEXP ? g_cnt[e] : T_TOKENS;
    if (m0 >= cnt) return;

    extern __shared__ char db[];

    const int tid  = threadIdx.x;
    const int lane = tid & 31;
    const int warp = tid >> 5;
    const int wm = warp & 1;
    const int wn = warp >> 1;

    const size_t arow = (AEXP ? (size_t)e * T_TOKENS : 0) + m0 + tid;
    const __half* aP = A + arow * K;
    const uint32_t aDst = smem_u32(db) + (uint32_t)(tid * ASTRIDE);

    const int bkr = tid >> 2;
    const int seg = (tid & 3) * CPT;
    const size_t eoff = AEXP ? (size_t)e * K * Ntot : 0;
    const __half* BP = B0 + eoff + n0 + seg + (size_t)bkr * Ntot;
    const uint32_t bDst = smem_u32(db) + (uint32_t)(A_BYTES + bkr * BSTR + seg * 2);

    auto issue = [&](int k0, int s) {
        const uint32_t so = (uint32_t)(s * STG);
        #pragma unroll
        for (int i = 0; i < 4; ++i) CP16(aDst + so + i * 16, aP + k0 + i * 8);
        const __half* bp = BP + (size_t)k0 * Ntot;
        #pragma unroll
        for (int i = 0; i < NCP; ++i) CP16(bDst + so + i * 16, bp + i * 8);
    };

    float acc[4][NJ][4];
    #pragma unroll
    for (int i = 0; i < 4; ++i)
        #pragma unroll
        for (int j = 0; j < NJ; ++j)
            #pragma unroll
            for (int v = 0; v < 4; ++v) acc[i][j][v] = 0.f;

    const int grp = lane >> 3;
    const int gl  = lane & 7;
    const int a_row_off = (grp & 1) * 8 + gl;
    const int a_col_off = (grp >> 1) * 8;
    const int b_row_off = (grp & 1) * 8 + gl;
    const int b_col_off = (grp >> 1) * 8;

    const int C = K / 32;
    issue(0, 0); CP_COMMIT();
    issue(32, 1); CP_COMMIT();
    issue(64, 2); CP_COMMIT();

    for (int c = 0; c < C; ++c) {
        CP_WAIT(2);
        __syncthreads();

        const uint32_t base = smem_u32(db) + (uint32_t)((c % 3) * STG);
        #pragma unroll
        for (int ks = 0; ks < 32; ks += 16) {
            uint32_t ah[4][4];
            #pragma unroll
            for (int mi = 0; mi < 4; ++mi) {
                const uint32_t ra = base + (uint32_t)((wm * 64 + mi * 16 + a_row_off) * ASTRIDE + (ks + a_col_off) * 2);
                ldsm_x4(ah[mi], ra);
            }
            #pragma unroll
            for (int g = 0; g < NW / 16; ++g) {
                uint32_t bh[4];
                const uint32_t rb = base + (uint32_t)(A_BYTES + (ks + b_row_off) * BSTR + (wn * NW + g * 16 + b_col_off) * 2);
                ldsm_x4_t(bh, rb);
                #pragma unroll
                for (int mi = 0; mi < 4; ++mi)
                    #pragma unroll
                    for (int half = 0; half < 2; ++half)
                        mma16816(acc[mi][g * 2 + half], ah[mi], bh[half * 2], bh[half * 2 + 1]);
            }
        }
        __syncthreads();
        if (c + 3 < C) issue((c + 3) * 32, c % 3);
        CP_COMMIT();
    }

    #pragma unroll
    for (int mi = 0; mi < 4; ++mi)
        #pragma unroll
        for (int h = 0; h < 2; ++h) {
            const int rl = wm * 64 + mi * 16 + (lane >> 2) + h * 8;
            const int r = m0 + rl;
            if (EPI == 1) {
                if (r >= cnt) continue;
                const int idx = e * T_TOKENS + r;
                const float w = g_wt[idx];
                float* orow = g_contrib + ((size_t)g_tok[idx] * 2 + g_slot[idx]) * H_DIM;
                #pragma unroll
                for (int nj = 0; nj < NJ; ++nj) {
                    const int c = n0 + wn * NW + nj * 8 + (lane & 3) * 2;
                    float2 o = {acc[mi][nj][h * 2] * w, acc[mi][nj][h * 2 + 1] * w};
                    *(float2*)(orow + c) = o;
                }
            } else {
                const float sg = g_sgate[r];
                #pragma unroll
                for (int nj = 0; nj < NJ; ++nj) {
                    const int c = n0 + wn * NW + nj * 8 + (lane & 3) * 2;
                    const float2 c0 = *(const float2*)(g_contrib + ((size_t)r * 2 + 0) * H_DIM + c);
                    const float2 c1 = *(const float2*)(g_contrib + ((size_t)r * 2 + 1) * H_DIM + c);
                    float2 o = {sg * acc[mi][nj][h * 2] + c0.x + c1.x,
                                sg * acc[mi][nj][h * 2 + 1] + c0.y + c1.y};
                    *(float2*)(outF + (size_t)r * H_DIM + c) = o;
                }
            }
        }
}

// ---------------------------------------------------------------------------
extern "C" void kernel_launch(void* const* d_in, const int* in_sizes, int n_in,
                              void* d_out, int out_size)
{
    const float* hidden        = (const float*)d_in[0];
    const float* gate_w        = (const float*)d_in[1];
    const float* w_gate        = (const float*)d_in[2];
    const float* w_up          = (const float*)d_in[3];
    const float* w_down        = (const float*)d_in[4];
    const float* sw_gate       = (const float*)d_in[5];
    const float* sw_up         = (const float*)d_in[6];
    const float* sw_down       = (const float*)d_in[7];
    const float* shared_gate_w = (const float*)d_in[8];

    float* out        = (float*)d_out;
    float* out_logits = out + (size_t)T_TOKENS * H_DIM;

    __half *hid, *act, *shact;
    __half *wg16, *wu16, *wd16, *swg16, *swu16, *swd16;
    cudaGetSymbolAddress((void**)&hid, g_hid);
    cudaGetSymbolAddress((void**)&act, g_act);
    cudaGetSymbolAddress((void**)&shact, g_shact);
    cudaGetSymbolAddress((void**)&wg16, g_wg16);
    cudaGetSymbolAddress((void**)&wu16, g_wu16);
    cudaGetSymbolAddress((void**)&wd16, g_wd16);
    cudaGetSymbolAddress((void**)&swg16, g_swg16);
    cudaGetSymbolAddress((void**)&swu16, g_swu16);
    cudaGetSymbolAddress((void**)&swd16, g_swd16);

    const int SM128 = 3 * (A_BYTES + 32 * (128 * 2 + 16));  // 56832
    const int SM64  = 3 * (A_BYTES + 32 * (64 * 2 + 16));   // 44544

    cudaFuncSetAttribute(gateup_fused,        cudaFuncAttributeMaxDynamicSharedMemorySize, SM128);
    cudaFuncSetAttribute(down_gemm<1,1,128>,  cudaFuncAttributeMaxDynamicSharedMemorySize, SM128);
    cudaFuncSetAttribute(down_gemm<0,2,64>,   cudaFuncAttributeMaxDynamicSharedMemorySize, SM64);

    zero_cnt_kernel<<<1, 32>>>();
    router_kernel<<<T_TOKENS, 256>>>(hidden, gate_w, shared_gate_w, out_logits);

    auto cvt = [&](const float* s, __half* d, size_t n) {
        int n4 = (int)(n / 4);
        int grid = (n4 + 255) / 256; if (grid > 4096) grid = 4096;
        cvt_kernel<<<grid, 256>>>(s, d, n4);
    };
    cvt(hidden,  hid,   (size_t)T_TOKENS * H_DIM);
    cvt(w_gate,  wg16,  (size_t)NE * H_DIM * I_DIM);
    cvt(w_up,    wu16,  (size_t)NE * H_DIM * I_DIM);
    cvt(w_down,  wd16,  (size_t)NE * I_DIM * H_DIM);
    cvt(sw_gate, swg16, (size_t)H_DIM * SI_DIM);
    cvt(sw_up,   swu16, (size_t)H_DIM * SI_DIM);
    cvt(sw_down, swd16, (size_t)SI_DIM * H_DIM);

    // fused expert+shared gate/up (wave-packed single launch)
    gateup_fused<<<GU_SH_BLOCKS + GU_EXP_BLOCKS, 128, SM128>>>(
        hid, wg16, wu16, swg16, swu16, act, shact);

    // expert down -> contrib scatter
    down_gemm<1,1,128><<<dim3(H_DIM / 128, T_TOKENS / 128, NE), 128, SM128>>>(
        act, wd16, nullptr, I_DIM, H_DIM);

    // shared down + combine -> out
    down_gemm<0,2,64><<<dim3(H_DIM / 64, T_TOKENS / 128, 1), 128, SM64>>>(
        shact, swd16, out, SI_DIM, H_DIM);
}